// round 5
// baseline (speedup 1.0000x reference)
#include <cuda_runtime.h>
#include <cstdint>

#define B_TOK 8192
#define D_IN  1024
#define D_OUT 1024
#define NE    16
#define TOPK  2
#define NH    64

// ---------------- device scratch (static allocations only) ----------------
__device__ int   g_cnt[NE];
__device__ int   g_dst[NE * B_TOK];              // dst slot = token*2 + k
__device__ float g_gw[NE * B_TOK];               // gate weight for that slot
__device__ float g_ybuf[B_TOK * TOPK * D_OUT];   // 64 MB slot-indexed partial outputs

// ---------------- helpers ----------------
__device__ __forceinline__ void cp16(void* s, const void* g) {
    uint32_t sa = (uint32_t)__cvta_generic_to_shared(s);
    asm volatile("cp.async.cg.shared.global [%0], [%1], 16;\n" :: "r"(sa), "l"(g));
}
__device__ __forceinline__ void cp_commit() { asm volatile("cp.async.commit_group;\n"); }
template<int N> __device__ __forceinline__ void cp_wait() {
    asm volatile("cp.async.wait_group %0;\n" :: "n"(N));
}

__device__ __forceinline__ void top2_insert(float v, int e, float& v0, int& i0,
                                            float& v1, int& i1) {
    if (v > v0 || (v == v0 && e < i0)) { v1 = v0; i1 = i0; v0 = v; i0 = e; }
    else if (v > v1 || (v == v1 && e < i1)) { v1 = v; i1 = e; }
}

// ---------------- kernel 0: reset counters ----------------
__global__ void reset_kernel() {
    if (threadIdx.x < NE) g_cnt[threadIdx.x] = 0;
}

// ---------------- kernel 1: gating + top-2 + expert list append ----------------
// block = 256 threads = 64 tokens x 4 expert-quads; grid = 8192/64 = 128
__global__ void __launch_bounds__(256) gate_kernel(
    const float* __restrict__ x, const float* __restrict__ Wg,
    const float* __restrict__ bg)
{
    __shared__ float Xs[64][65];   // 64 tokens x 64-k chunk (pad 65 -> conflict free)
    __shared__ float Wgs[64][16];  // k chunk x experts
    const int tid = threadIdx.x;
    const int tl  = tid >> 2;      // token-in-block 0..63
    const int eb  = tid & 3;       // expert quad 0..3
    const int t0  = blockIdx.x * 64;

    float tot0 = 0.f, tot1 = 0.f, tot2 = 0.f, tot3 = 0.f;

    #pragma unroll 1
    for (int k0 = 0; k0 < D_IN; k0 += 64) {
        #pragma unroll
        for (int i = 0; i < 4; i++) {
            int f = tid + i * 256;          // 0..1023 float4 tasks
            int r = f >> 4, c4 = f & 15;
            float4 v = *(const float4*)&x[(t0 + r) * D_IN + k0 + c4 * 4];
            Xs[r][c4*4 + 0] = v.x; Xs[r][c4*4 + 1] = v.y;
            Xs[r][c4*4 + 2] = v.z; Xs[r][c4*4 + 3] = v.w;
        }
        {
            int r = tid >> 2, c4 = tid & 3;
            *(float4*)&Wgs[r][c4*4] = *(const float4*)&Wg[(k0 + r) * NE + c4 * 4];
        }
        __syncthreads();
        // chunk-local accumulators (keeps logits within ~1e-6 of jax)
        float a0 = 0.f, a1 = 0.f, a2 = 0.f, a3 = 0.f;
        #pragma unroll 16
        for (int kk = 0; kk < 64; kk++) {
            float xv = Xs[tl][kk];
            float4 w = *(const float4*)&Wgs[kk][eb * 4];
            a0 += xv * w.x; a1 += xv * w.y; a2 += xv * w.z; a3 += xv * w.w;
        }
        tot0 += a0; tot1 += a1; tot2 += a2; tot3 += a3;
        __syncthreads();
    }
    float4 bgv = *(const float4*)&bg[eb * 4];
    tot0 += bgv.x; tot1 += bgv.y; tot2 += bgv.z; tot3 += bgv.w;

    // local top-2 among my 4 experts (jax tie-break: lower index wins)
    float v0 = -3.402823466e38f, v1 = -3.402823466e38f;
    int   i0 = NE, i1 = NE;
    top2_insert(tot0, eb * 4 + 0, v0, i0, v1, i1);
    top2_insert(tot1, eb * 4 + 1, v0, i0, v1, i1);
    top2_insert(tot2, eb * 4 + 2, v0, i0, v1, i1);
    top2_insert(tot3, eb * 4 + 3, v0, i0, v1, i1);

    // butterfly merge across the 4 lanes of this token
    const unsigned m = 0xFFFFFFFFu;
    #pragma unroll
    for (int d = 1; d < 4; d <<= 1) {
        float ov0 = __shfl_xor_sync(m, v0, d);
        int   oi0 = __shfl_xor_sync(m, i0, d);
        float ov1 = __shfl_xor_sync(m, v1, d);
        int   oi1 = __shfl_xor_sync(m, i1, d);
        top2_insert(ov0, oi0, v0, i0, v1, i1);
        top2_insert(ov1, oi1, v0, i0, v1, i1);
    }

    if (eb == 0) {
        int tok = t0 + tl;
        float r   = expf(v1 - v0);       // softmax-over-top2 == renormalized probs
        float inv = 1.0f / (1.0f + r);
        int p0 = atomicAdd(&g_cnt[i0], 1);
        g_dst[i0 * B_TOK + p0] = tok * 2;
        g_gw [i0 * B_TOK + p0] = inv;
        int p1 = atomicAdd(&g_cnt[i1], 1);
        g_dst[i1 * B_TOK + p1] = tok * 2 + 1;
        g_gw [i1 * B_TOK + p1] = r * inv;
    }
}

// ---------------- kernel 2: grouped expert MLP ----------------
// grid = (128 token-tiles, 16 experts), block = 256, dyn smem = 80 KB
__global__ void __launch_bounds__(256, 2) expert_kernel(
    const float* __restrict__ x,  const float* __restrict__ W1,
    const float* __restrict__ b1, const float* __restrict__ W2,
    const float* __restrict__ b2)
{
    const int e    = blockIdx.y;
    const int n    = g_cnt[e];
    const int base = blockIdx.x * 64;
    if (base >= n) return;
    const int tid = threadIdx.x;

    __shared__ int   s_dst[64];
    __shared__ int   s_tok[64];
    __shared__ float s_w[64];
    extern __shared__ float sm[];
    float* Hs  = sm;               // [64][64]              16 KB
    float* Xs  = sm + 4096;        // [2][64][32]           16 KB  (phase A)
    float* W1s = sm + 8192;        // [2][32][64]           16 KB  (phase A)
    float* W2s = sm + 4096;        // [2][64][128]          64 KB  (phase B, overlaps A)

    if (tid < 64) {
        int slot = base + tid;
        if (slot < n) {
            int d = g_dst[e * B_TOK + slot];
            s_dst[tid] = d; s_tok[tid] = d >> 1;
            s_w[tid] = g_gw[e * B_TOK + slot];
        } else { s_dst[tid] = -1; s_tok[tid] = 0; s_w[tid] = 0.f; }
    }
    __syncthreads();

    // ======== Phase A: H[64][64] = relu(Xgather[64][1024] @ W1[e] + b1[e]) ========
    const int ty = tid >> 4, tx = tid & 15;     // 16x16 thread grid, 4x4 tile each
    float acc[4][4];
    #pragma unroll
    for (int i = 0; i < 4; i++)
        #pragma unroll
        for (int j = 0; j < 4; j++) acc[i][j] = 0.f;

    auto loadA = [&](int c, int s) {
        const int k0 = c * 32;
        #pragma unroll
        for (int i = 0; i < 2; i++) {
            int f = tid + i * 256;               // 512 float4: Xs
            int t = f >> 3, c4 = f & 7;
            cp16(&Xs[s * 2048 + t * 32 + c4 * 4],
                 &x[s_tok[t] * D_IN + k0 + c4 * 4]);
        }
        #pragma unroll
        for (int i = 0; i < 2; i++) {
            int f = tid + i * 256;               // 512 float4: W1s
            int kc = f >> 4, c4 = f & 15;
            cp16(&W1s[s * 2048 + kc * 64 + c4 * 4],
                 &W1[(e * D_IN + k0 + kc) * NH + c4 * 4]);
        }
    };

    loadA(0, 0); cp_commit();
    loadA(1, 1); cp_commit();
    #pragma unroll 1
    for (int c = 0; c < 32; c++) {
        cp_wait<1>(); __syncthreads();
        const float* Xp = Xs  + (c & 1) * 2048;
        const float* Wp = W1s + (c & 1) * 2048;
        #pragma unroll
        for (int kk = 0; kk < 32; kk += 4) {
            float4 xq[4], wq[4];
            #pragma unroll
            for (int i = 0; i < 4; i++) xq[i] = *(const float4*)&Xp[(ty * 4 + i) * 32 + kk];
            #pragma unroll
            for (int q = 0; q < 4; q++) wq[q] = *(const float4*)&Wp[(kk + q) * 64 + tx * 4];
            #pragma unroll
            for (int q = 0; q < 4; q++) {
                #pragma unroll
                for (int i = 0; i < 4; i++) {
                    float xv = (q == 0) ? xq[i].x : (q == 1) ? xq[i].y
                             : (q == 2) ? xq[i].z : xq[i].w;
                    acc[i][0] += xv * wq[q].x; acc[i][1] += xv * wq[q].y;
                    acc[i][2] += xv * wq[q].z; acc[i][3] += xv * wq[q].w;
                }
            }
        }
        __syncthreads();
        if (c + 2 < 32) loadA(c + 2, c & 1);
        cp_commit();
    }

    // bias + relu -> Hs
    {
        float4 bv = *(const float4*)&b1[e * NH + tx * 4];
        #pragma unroll
        for (int i = 0; i < 4; i++) {
            float4 h;
            h.x = fmaxf(acc[i][0] + bv.x, 0.f);
            h.y = fmaxf(acc[i][1] + bv.y, 0.f);
            h.z = fmaxf(acc[i][2] + bv.z, 0.f);
            h.w = fmaxf(acc[i][3] + bv.w, 0.f);
            *(float4*)&Hs[(ty * 4 + i) * 64 + tx * 4] = h;
        }
    }
    __syncthreads();

    // ======== Phase B: Y[64][1024] = w * (H @ W2[e] + b2[e]) -> ybuf slots ========
    const int ob = tid & 15, tb = tid >> 4;     // 4 tokens x 8 out-cols per thread

    auto loadB = [&](int c, int s) {
        const int oc0 = c * 128;
        #pragma unroll
        for (int i = 0; i < 8; i++) {
            int f = tid + i * 256;               // 2048 float4: W2s
            int hh = f >> 5, c4 = f & 31;
            cp16(&W2s[s * 8192 + hh * 128 + c4 * 4],
                 &W2[(e * NH + hh) * D_OUT + oc0 + c4 * 4]);
        }
    };

    loadB(0, 0); cp_commit();
    loadB(1, 1); cp_commit();
    #pragma unroll 1
    for (int c = 0; c < 8; c++) {
        cp_wait<1>(); __syncthreads();
        float a2[4][8];
        #pragma unroll
        for (int i = 0; i < 4; i++)
            #pragma unroll
            for (int j = 0; j < 8; j++) a2[i][j] = 0.f;
        const float* Wp = W2s + (c & 1) * 8192;
        #pragma unroll 4
        for (int hh = 0; hh < 64; hh += 4) {
            float4 hq[4], wa[4], wb[4];
            #pragma unroll
            for (int i = 0; i < 4; i++) hq[i] = *(const float4*)&Hs[(tb * 4 + i) * 64 + hh];
            #pragma unroll
            for (int q = 0; q < 4; q++) {
                wa[q] = *(const float4*)&Wp[(hh + q) * 128 + ob * 8];
                wb[q] = *(const float4*)&Wp[(hh + q) * 128 + ob * 8 + 4];
            }
            #pragma unroll
            for (int q = 0; q < 4; q++) {
                #pragma unroll
                for (int i = 0; i < 4; i++) {
                    float hv = (q == 0) ? hq[i].x : (q == 1) ? hq[i].y
                             : (q == 2) ? hq[i].z : hq[i].w;
                    a2[i][0] += hv * wa[q].x; a2[i][1] += hv * wa[q].y;
                    a2[i][2] += hv * wa[q].z; a2[i][3] += hv * wa[q].w;
                    a2[i][4] += hv * wb[q].x; a2[i][5] += hv * wb[q].y;
                    a2[i][6] += hv * wb[q].z; a2[i][7] += hv * wb[q].w;
                }
            }
        }
        // epilogue: + b2, * gate weight, store to slot
        const int oc0 = c * 128;
        float4 b2a = *(const float4*)&b2[e * D_OUT + oc0 + ob * 8];
        float4 b2b = *(const float4*)&b2[e * D_OUT + oc0 + ob * 8 + 4];
        #pragma unroll
        for (int i = 0; i < 4; i++) {
            int dst = s_dst[tb * 4 + i];
            if (dst >= 0) {
                float w = s_w[tb * 4 + i];
                float4 o1, o2;
                o1.x = w * (a2[i][0] + b2a.x); o1.y = w * (a2[i][1] + b2a.y);
                o1.z = w * (a2[i][2] + b2a.z); o1.w = w * (a2[i][3] + b2a.w);
                o2.x = w * (a2[i][4] + b2b.x); o2.y = w * (a2[i][5] + b2b.y);
                o2.z = w * (a2[i][6] + b2b.z); o2.w = w * (a2[i][7] + b2b.w);
                *(float4*)&g_ybuf[dst * D_OUT + oc0 + ob * 8]     = o1;
                *(float4*)&g_ybuf[dst * D_OUT + oc0 + ob * 8 + 4] = o2;
            }
        }
        __syncthreads();
        if (c + 2 < 8) loadB(c + 2, c & 1);
        cp_commit();
    }
}

// ---------------- kernel 3: combine the two expert contributions ----------------
__global__ void __launch_bounds__(256) combine_kernel(float* __restrict__ out) {
    int idx = blockIdx.x * 256 + threadIdx.x;   // float4 index
    int t = idx >> 8;                            // 256 float4 per output row
    int c = idx & 255;
    float4 a = *((const float4*)&g_ybuf[(t * 2    ) * D_OUT] + c);
    float4 b = *((const float4*)&g_ybuf[(t * 2 + 1) * D_OUT] + c);
    float4 r;
    r.x = a.x + b.x; r.y = a.y + b.y; r.z = a.z + b.z; r.w = a.w + b.w;
    ((float4*)out)[idx] = r;
}

// ---------------- launch ----------------
extern "C" void kernel_launch(void* const* d_in, const int* in_sizes, int n_in,
                              void* d_out, int out_size) {
    const float* x  = (const float*)d_in[0];
    const float* Wg = (const float*)d_in[1];
    const float* bg = (const float*)d_in[2];
    const float* W1 = (const float*)d_in[3];
    const float* b1 = (const float*)d_in[4];
    const float* W2 = (const float*)d_in[5];
    const float* b2 = (const float*)d_in[6];
    float* out = (float*)d_out;

    cudaFuncSetAttribute(expert_kernel,
                         cudaFuncAttributeMaxDynamicSharedMemorySize, 81920);

    reset_kernel<<<1, 32>>>();
    gate_kernel<<<B_TOK / 64, 256>>>(x, Wg, bg);
    expert_kernel<<<dim3(128, NE), 256, 81920>>>(x, W1, b1, W2, b2);
    combine_kernel<<<(B_TOK * D_OUT / 4) / 256, 256>>>(out);
}